// round 3
// baseline (speedup 1.0000x reference)
#include <cuda_runtime.h>

// Problem constants
#define T_TOK 16384
#define HID   2048
#define IEXP  1024
#define NEXP  8
#define VOCAB_SZ 100000
#define TPE   12500   // VOCAB / NUM_EXPERTS

// ---------------- device scratch (allocation-free: static __device__ globals) ----
__device__ float g_scr[(size_t)T_TOK * IEXP];   // gate outputs, then h = silu(g)*u
__device__ float u_scr[(size_t)T_TOK * IEXP];   // up outputs
__device__ int   perm_d[T_TOK];                 // bucketed token indices (compact)
__device__ int   expert_d[T_TOK];
__device__ int   cnt_d[NEXP];
__device__ int   base_d[NEXP];
__device__ int   cur_d[NEXP];

// ---------------- routing ----------------
__global__ void k_zero() {
    if (threadIdx.x < NEXP) { cnt_d[threadIdx.x] = 0; cur_d[threadIdx.x] = 0; }
}

__global__ void k_count(const int* __restrict__ ids) {
    int t = blockIdx.x * blockDim.x + threadIdx.x;
    if (t >= T_TOK) return;
    int v = ids[t];
    if (v < 0) v = 0;
    if (v > VOCAB_SZ - 1) v = VOCAB_SZ - 1;
    int e = v / TPE;
    if (e > NEXP - 1) e = NEXP - 1;
    expert_d[t] = e;
    atomicAdd(&cnt_d[e], 1);
}

__global__ void k_scan() {
    int s = 0;
    for (int e = 0; e < NEXP; e++) { base_d[e] = s; s += cnt_d[e]; }
}

__global__ void k_scatter() {
    int t = blockIdx.x * blockDim.x + threadIdx.x;
    if (t >= T_TOK) return;
    int e = expert_d[t];
    int p = base_d[e] + atomicAdd(&cur_d[e], 1);
    perm_d[p] = t;
}

// ---------------- tf32 helpers ----------------
__device__ __forceinline__ unsigned f2t(float f) {
    unsigned u;
    asm("cvt.rna.tf32.f32 %0, %1;" : "=r"(u) : "f"(f));
    return u;
}

__device__ __forceinline__ void mma_t(float* c, const unsigned* a, const unsigned* b) {
    asm volatile(
        "mma.sync.aligned.m16n8k8.row.col.f32.tf32.tf32.f32 "
        "{%0,%1,%2,%3},{%4,%5,%6,%7},{%8,%9},{%0,%1,%2,%3};"
        : "+f"(c[0]), "+f"(c[1]), "+f"(c[2]), "+f"(c[3])
        : "r"(a[0]), "r"(a[1]), "r"(a[2]), "r"(a[3]), "r"(b[0]), "r"(b[1]));
}

// ---------------- tiled GEMM (128x128 tile, K-chunk 32, 8 warps) ----------------
// mode 0: C = gather(X) @ gate[e]  -> g_scr   (A = Aext gathered via perm, KDIM=HID, NDIM=IEXP)
// mode 1: C = gather(X) @ up[e]    -> u_scr
// mode 2: C = h(g_scr) @ down[e]   -> Cext, scattered to out rows by token id (KDIM=IEXP, NDIM=HID)
__global__ __launch_bounds__(256)
void k_gemm(const float* __restrict__ Aext, const float* __restrict__ Bw,
            float* __restrict__ Cext, int KDIM, int NDIM, int mode)
{
    int e   = blockIdx.z;
    int cnt = cnt_d[e];
    int m0  = blockIdx.y * 128;
    if (m0 >= cnt) return;                 // uniform across block (pre-barrier)
    int n0    = blockIdx.x * 128;
    int valid = cnt - m0; if (valid > 128) valid = 128;
    int pbase = base_d[e] + m0;

    __shared__ unsigned As[128][36];       // padded: frag loads conflict-free
    __shared__ unsigned Bs[32][132];
    __shared__ int      toks[128];

    int tid = threadIdx.x;
    if (tid < 128) toks[tid] = perm_d[pbase + (tid < valid ? tid : valid - 1)];
    __syncthreads();

    const float* A  = (mode == 2) ? g_scr : Aext;
    const float* Be = Bw + (size_t)e * KDIM * NDIM;

    float acc[2][8][4];
#pragma unroll
    for (int i = 0; i < 2; i++)
#pragma unroll
        for (int j = 0; j < 8; j++)
#pragma unroll
            for (int k = 0; k < 4; k++) acc[i][j][k] = 0.f;

    int lane = tid & 31, wid = tid >> 5;
    int wm = (wid >> 1) * 32;   // warp M offset: 0,32,64,96
    int wn = (wid & 1) * 64;    // warp N offset: 0,64

    // global load assignments
    int ar = tid >> 1, ac = (tid & 1) * 16;     // A: 128 rows x 32 cols
    int br = tid >> 3, bc = (tid & 7) * 16;     // B: 32 rows x 128 cols
    int arc = ar < valid ? ar : valid - 1;
    const float* Abase = (mode == 2)
        ? (A + (size_t)(pbase + arc) * KDIM + ac)
        : (A + (size_t)toks[ar] * KDIM + ac);
    const float* Bbase = Be + (size_t)br * NDIM + n0 + bc;

    for (int k0 = 0; k0 < KDIM; k0 += 32) {
        // stage A tile
        {
            const float* s = Abase + k0;
            float4 v0 = *(const float4*)(s);
            float4 v1 = *(const float4*)(s + 4);
            float4 v2 = *(const float4*)(s + 8);
            float4 v3 = *(const float4*)(s + 12);
            uint4* d = (uint4*)&As[ar][ac];
            d[0] = make_uint4(f2t(v0.x), f2t(v0.y), f2t(v0.z), f2t(v0.w));
            d[1] = make_uint4(f2t(v1.x), f2t(v1.y), f2t(v1.z), f2t(v1.w));
            d[2] = make_uint4(f2t(v2.x), f2t(v2.y), f2t(v2.z), f2t(v2.w));
            d[3] = make_uint4(f2t(v3.x), f2t(v3.y), f2t(v3.z), f2t(v3.w));
        }
        // stage B tile
        {
            const float* s = Bbase + (size_t)k0 * NDIM;
            float4 v0 = *(const float4*)(s);
            float4 v1 = *(const float4*)(s + 4);
            float4 v2 = *(const float4*)(s + 8);
            float4 v3 = *(const float4*)(s + 12);
            uint4* d = (uint4*)&Bs[br][bc];
            d[0] = make_uint4(f2t(v0.x), f2t(v0.y), f2t(v0.z), f2t(v0.w));
            d[1] = make_uint4(f2t(v1.x), f2t(v1.y), f2t(v1.z), f2t(v1.w));
            d[2] = make_uint4(f2t(v2.x), f2t(v2.y), f2t(v2.z), f2t(v2.w));
            d[3] = make_uint4(f2t(v3.x), f2t(v3.y), f2t(v3.z), f2t(v3.w));
        }
        __syncthreads();

#pragma unroll
        for (int kk = 0; kk < 4; kk++) {
            unsigned af[2][4];
            int r0 = wm + (lane >> 2);
            int c0 = kk * 8 + (lane & 3);
#pragma unroll
            for (int mi = 0; mi < 2; mi++) {
                af[mi][0] = As[r0 + mi * 16][c0];
                af[mi][1] = As[r0 + mi * 16 + 8][c0];
                af[mi][2] = As[r0 + mi * 16][c0 + 4];
                af[mi][3] = As[r0 + mi * 16 + 8][c0 + 4];
            }
            unsigned bf[8][2];
            int kr = kk * 8 + (lane & 3);
            int nc = wn + (lane >> 2);
#pragma unroll
            for (int ni = 0; ni < 8; ni++) {
                bf[ni][0] = Bs[kr][nc + ni * 8];
                bf[ni][1] = Bs[kr + 4][nc + ni * 8];
            }
#pragma unroll
            for (int mi = 0; mi < 2; mi++)
#pragma unroll
                for (int ni = 0; ni < 8; ni++)
                    mma_t(acc[mi][ni], af[mi], bf[ni]);
        }
        __syncthreads();
    }

    // epilogue
#pragma unroll
    for (int mi = 0; mi < 2; mi++) {
        int rb = wm + mi * 16 + (lane >> 2);
#pragma unroll
        for (int ni = 0; ni < 8; ni++) {
            int cc = n0 + wn + ni * 8 + (lane & 3) * 2;
            if (rb < valid) {
                float* Crow;
                if (mode == 0)      Crow = g_scr + (size_t)(pbase + rb) * IEXP;
                else if (mode == 1) Crow = u_scr + (size_t)(pbase + rb) * IEXP;
                else                Crow = Cext + (size_t)toks[rb] * NDIM;
                Crow[cc]     = acc[mi][ni][0];
                Crow[cc + 1] = acc[mi][ni][1];
            }
            if (rb + 8 < valid) {
                float* Crow;
                if (mode == 0)      Crow = g_scr + (size_t)(pbase + rb + 8) * IEXP;
                else if (mode == 1) Crow = u_scr + (size_t)(pbase + rb + 8) * IEXP;
                else                Crow = Cext + (size_t)toks[rb + 8] * NDIM;
                Crow[cc]     = acc[mi][ni][2];
                Crow[cc + 1] = acc[mi][ni][3];
            }
        }
    }
}

// ---------------- h = silu(g) * u (in place into g_scr) ----------------
__global__ void k_silu() {
    size_t i = ((size_t)blockIdx.x * blockDim.x + threadIdx.x) * 4;
    float4 g = *(float4*)&g_scr[i];
    float4 u = *(float4*)&u_scr[i];
    float4 h;
    h.x = g.x / (1.f + expf(-g.x)) * u.x;
    h.y = g.y / (1.f + expf(-g.y)) * u.y;
    h.z = g.z / (1.f + expf(-g.z)) * u.z;
    h.w = g.w / (1.f + expf(-g.w)) * u.w;
    *(float4*)&g_scr[i] = h;
}

// ---------------- launch ----------------
extern "C" void kernel_launch(void* const* d_in, const int* in_sizes, int n_in,
                              void* d_out, int out_size)
{
    const float* hs   = (const float*)d_in[0];
    const int*   ids  = (const int*)d_in[1];      // int32 (JAX x64 disabled)
    const float* gate = (const float*)d_in[2];
    const float* up   = (const float*)d_in[3];
    const float* down = (const float*)d_in[4];
    float*       out  = (float*)d_out;

    k_zero<<<1, 32>>>();
    k_count<<<T_TOK / 256, 256>>>(ids);
    k_scan<<<1, 1>>>();
    k_scatter<<<T_TOK / 256, 256>>>();

    dim3 blk(256);
    // g = X @ gate[e]
    k_gemm<<<dim3(IEXP / 128, T_TOK / 128, NEXP), blk>>>(hs, gate, out, HID, IEXP, 0);
    // u = X @ up[e]
    k_gemm<<<dim3(IEXP / 128, T_TOK / 128, NEXP), blk>>>(hs, up, out, HID, IEXP, 1);
    // h = silu(g) * u
    k_silu<<<(T_TOK * IEXP) / 1024, 256>>>();
    // out = h @ down[e] (scatter by token)
    k_gemm<<<dim3(HID / 128, T_TOK / 128, NEXP), blk>>>(hs, down, out, IEXP, HID, 2);
}

// round 4
// speedup vs baseline: 1.1424x; 1.1424x over previous
#include <cuda_runtime.h>
#include <math.h>

// Problem constants
#define T_TOK 16384
#define HID   2048
#define IEXP  1024
#define NEXP  8
#define VOCAB_SZ 100000
#define TPE   12500

// SMEM layout (dynamic): 2-stage A + 2-stage B + toks
#define ASTRIDE 36
#define BSTRIDE 132
#define AWORDS (128 * ASTRIDE)            // 4608 words / stage
#define BWORDS (32 * BSTRIDE)             // 4224 words / stage
#define SMEM_WORDS (2 * AWORDS + 2 * BWORDS)   // 17664
#define SMEM_BYTES (SMEM_WORDS * 4 + 128 * 4)  // 71168 B

// ---------------- device scratch ----------------
__device__ float g_scr[(size_t)T_TOK * IEXP];   // gate out, then h = silu(g)*u
__device__ int   perm_d[T_TOK];
__device__ int   expert_d[T_TOK];
__device__ int   cnt_d[NEXP];
__device__ int   base_d[NEXP];
__device__ int   cur_d[NEXP];

// ---------------- routing ----------------
__global__ void k_zero() {
    if (threadIdx.x < NEXP) { cnt_d[threadIdx.x] = 0; cur_d[threadIdx.x] = 0; }
}

__global__ void k_count(const int* __restrict__ ids) {
    int t = blockIdx.x * blockDim.x + threadIdx.x;
    if (t >= T_TOK) return;
    int v = ids[t];
    if (v < 0) v = 0;
    if (v > VOCAB_SZ - 1) v = VOCAB_SZ - 1;
    int e = v / TPE;
    if (e > NEXP - 1) e = NEXP - 1;
    expert_d[t] = e;
    atomicAdd(&cnt_d[e], 1);
}

__global__ void k_scan() {
    int s = 0;
    for (int e = 0; e < NEXP; e++) { base_d[e] = s; s += cnt_d[e]; }
}

__global__ void k_scatter() {
    int t = blockIdx.x * blockDim.x + threadIdx.x;
    if (t >= T_TOK) return;
    int e = expert_d[t];
    int p = base_d[e] + atomicAdd(&cur_d[e], 1);
    perm_d[p] = t;
}

// ---------------- helpers ----------------
__device__ __forceinline__ unsigned f2t(float f) {
    unsigned u;
    asm("cvt.rna.tf32.f32 %0, %1;" : "=r"(u) : "f"(f));
    return u;
}

__device__ __forceinline__ void mma_t(float* c, const unsigned* a, const unsigned* b) {
    asm volatile(
        "mma.sync.aligned.m16n8k8.row.col.f32.tf32.tf32.f32 "
        "{%0,%1,%2,%3},{%4,%5,%6,%7},{%8,%9},{%0,%1,%2,%3};"
        : "+f"(c[0]), "+f"(c[1]), "+f"(c[2]), "+f"(c[3])
        : "r"(a[0]), "r"(a[1]), "r"(a[2]), "r"(a[3]), "r"(b[0]), "r"(b[1]));
}

__device__ __forceinline__ void cp16(unsigned dst, const float* src) {
    asm volatile("cp.async.cg.shared.global [%0], [%1], 16;" :: "r"(dst), "l"(src));
}

// ---------------- pipelined tiled GEMM (128x128 tile, K-chunk 32, 2 stages) ----
// mode 0: g = gather(X) @ gate[e]                       -> g_scr
// mode 1: u = gather(X) @ up[e]; h = silu(g)*u          -> g_scr (fused, in place)
// mode 2: out = h @ down[e], scattered back by token id -> Cext
__global__ __launch_bounds__(256)
void k_gemm(const float* __restrict__ Aext, const float* __restrict__ Bw,
            float* __restrict__ Cext, int KDIM, int NDIM, int mode)
{
    extern __shared__ unsigned smw[];

    int e   = blockIdx.z;
    int cnt = cnt_d[e];
    int m0  = blockIdx.y * 128;
    if (m0 >= cnt) return;                 // uniform per block
    int n0    = blockIdx.x * 128;
    int valid = cnt - m0; if (valid > 128) valid = 128;
    int pbase = base_d[e] + m0;
    int tid   = threadIdx.x;

    int* toks = (int*)(smw + SMEM_WORDS);
    if (tid < 128) toks[tid] = perm_d[pbase + (tid < valid ? tid : valid - 1)];
    __syncthreads();

    const float* Be = Bw + (size_t)e * KDIM * NDIM;

    // per-thread staging assignments
    int ar = tid >> 1, acol = (tid & 1) * 16;     // A: 2 thr/row, 64B each
    int br = tid >> 3, bcol = (tid & 7) * 16;     // B: 8 thr/row, 64B each
    int arc = ar < valid ? ar : valid - 1;
    const float* Arow = (mode == 2)
        ? (g_scr + (size_t)(pbase + arc) * KDIM + acol)
        : (Aext + (size_t)toks[ar] * KDIM + acol);
    const float* Brow = Be + (size_t)br * NDIM + n0 + bcol;

    unsigned smem_u32 = (unsigned)__cvta_generic_to_shared(smw);
    unsigned aDst0 = smem_u32 + (ar * ASTRIDE + acol) * 4;
    unsigned bDst0 = smem_u32 + (2 * AWORDS + br * BSTRIDE + bcol) * 4;

    auto stage = [&](int s, int k0) {
        unsigned ad = aDst0 + s * (AWORDS * 4);
        const float* as = Arow + k0;
#pragma unroll
        for (int j = 0; j < 4; j++) cp16(ad + j * 16, as + j * 4);
        unsigned bd = bDst0 + s * (BWORDS * 4);
        const float* bs = Brow + (size_t)k0 * NDIM;
#pragma unroll
        for (int j = 0; j < 4; j++) cp16(bd + j * 16, bs + j * 4);
    };

    float acc[2][8][4];
#pragma unroll
    for (int i = 0; i < 2; i++)
#pragma unroll
        for (int j = 0; j < 8; j++)
#pragma unroll
            for (int k = 0; k < 4; k++) acc[i][j][k] = 0.f;

    int lane = tid & 31, wid = tid >> 5;
    int wm = (wid >> 1) * 32;   // warp M: 0,32,64,96
    int wn = (wid & 1) * 64;    // warp N: 0,64

    // prologue: fill both stages
    stage(0, 0);  asm volatile("cp.async.commit_group;");
    stage(1, 32); asm volatile("cp.async.commit_group;");

    int s = 0;
    for (int k0 = 0; k0 < KDIM; k0 += 32) {
        asm volatile("cp.async.wait_group 1;");
        __syncthreads();

        const unsigned* Asm = smw + s * AWORDS;
        const unsigned* Bsm = smw + 2 * AWORDS + s * BWORDS;

#pragma unroll
        for (int kk = 0; kk < 4; kk++) {
            unsigned af[2][4];
            int r0 = wm + (lane >> 2);
            int c0 = kk * 8 + (lane & 3);
#pragma unroll
            for (int mi = 0; mi < 2; mi++) {
                af[mi][0] = f2t(__uint_as_float(Asm[(r0 + mi * 16) * ASTRIDE + c0]));
                af[mi][1] = f2t(__uint_as_float(Asm[(r0 + mi * 16 + 8) * ASTRIDE + c0]));
                af[mi][2] = f2t(__uint_as_float(Asm[(r0 + mi * 16) * ASTRIDE + c0 + 4]));
                af[mi][3] = f2t(__uint_as_float(Asm[(r0 + mi * 16 + 8) * ASTRIDE + c0 + 4]));
            }
            unsigned bf[8][2];
            int kr = kk * 8 + (lane & 3);
            int nc = wn + (lane >> 2);
#pragma unroll
            for (int ni = 0; ni < 8; ni++) {
                bf[ni][0] = f2t(__uint_as_float(Bsm[kr * BSTRIDE + nc + ni * 8]));
                bf[ni][1] = f2t(__uint_as_float(Bsm[(kr + 4) * BSTRIDE + nc + ni * 8]));
            }
#pragma unroll
            for (int mi = 0; mi < 2; mi++)
#pragma unroll
                for (int ni = 0; ni < 8; ni++)
                    mma_t(acc[mi][ni], af[mi], bf[ni]);
        }
        __syncthreads();

        if (k0 + 64 < KDIM) stage(s, k0 + 64);
        asm volatile("cp.async.commit_group;");   // commit even if empty: keeps accounting
        s ^= 1;
    }

    // epilogue
#pragma unroll
    for (int mi = 0; mi < 2; mi++) {
        int rb = wm + mi * 16 + (lane >> 2);
#pragma unroll
        for (int ni = 0; ni < 8; ni++) {
            int cc = n0 + wn + ni * 8 + (lane & 3) * 2;
#pragma unroll
            for (int h = 0; h < 2; h++) {
                int r = rb + h * 8;
                if (r < valid) {
                    float v0 = acc[mi][ni][h * 2], v1 = acc[mi][ni][h * 2 + 1];
                    if (mode == 0) {
                        float* row = g_scr + (size_t)(pbase + r) * IEXP;
                        row[cc] = v0; row[cc + 1] = v1;
                    } else if (mode == 1) {
                        float* row = g_scr + (size_t)(pbase + r) * IEXP;
                        float g0 = row[cc], g1 = row[cc + 1];
                        row[cc]     = g0 / (1.f + expf(-g0)) * v0;
                        row[cc + 1] = g1 / (1.f + expf(-g1)) * v1;
                    } else {
                        float* row = Cext + (size_t)toks[r] * NDIM;
                        row[cc] = v0; row[cc + 1] = v1;
                    }
                }
            }
        }
    }
}

// ---------------- launch ----------------
extern "C" void kernel_launch(void* const* d_in, const int* in_sizes, int n_in,
                              void* d_out, int out_size)
{
    const float* hs   = (const float*)d_in[0];
    const int*   ids  = (const int*)d_in[1];
    const float* gate = (const float*)d_in[2];
    const float* up   = (const float*)d_in[3];
    const float* down = (const float*)d_in[4];
    float*       out  = (float*)d_out;

    cudaFuncSetAttribute(k_gemm, cudaFuncAttributeMaxDynamicSharedMemorySize, SMEM_BYTES);

    k_zero<<<1, 32>>>();
    k_count<<<T_TOK / 256, 256>>>(ids);
    k_scan<<<1, 1>>>();
    k_scatter<<<T_TOK / 256, 256>>>();

    // g = X @ gate[e]
    k_gemm<<<dim3(IEXP / 128, T_TOK / 128, NEXP), 256, SMEM_BYTES>>>(hs, gate, out, HID, IEXP, 0);
    // u = X @ up[e]; h = silu(g)*u fused in epilogue
    k_gemm<<<dim3(IEXP / 128, T_TOK / 128, NEXP), 256, SMEM_BYTES>>>(hs, up, out, HID, IEXP, 1);
    // out = h @ down[e], scatter rows by token id
    k_gemm<<<dim3(HID / 128, T_TOK / 128, NEXP), 256, SMEM_BYTES>>>(hs, down, out, IEXP, HID, 2);
}

// round 6
// speedup vs baseline: 1.4309x; 1.2525x over previous
#include <cuda_runtime.h>
#include <cstdint>

#define T_TOK 16384
#define HID   2048
#define IEXP  1024
#define NEXP  8
#define VOCAB_SZ 100000
#define TPE   12500

// ---- fused gate/up kernel tiles ----
#define BM 128
#define BNF 64            // per-matrix N tile (gate and up each)
#define BK 32
#define ASTR 36           // A smem stride (words), conflict-free
#define BSTR 72           // B smem stride (words), 72%32=8 -> conflict-free
#define AW (BM * ASTR)    // 4608 words
#define BW (BK * BSTR)    // 2304 words
#define STGW (AW + 2 * BW)  // 9216 words per stage
#define NSTAGE 3
#define SMEMW_F (NSTAGE * STGW)               // 27648 words
#define SMEMB_F (SMEMW_F * 4 + 512 + 128)     // + toks + pad

// ---- down-proj kernel tiles ----
#define BN3 128
#define B3STR 136         // 136%32=8 -> conflict-free
#define B3W (BK * B3STR)  // 4352 words
#define STG3W (AW + B3W)  // 8960 words
#define SMEMB_3 (NSTAGE * STG3W * 4 + 512 + 128)

// ---------------- device scratch ----------------
__device__ float h_scr[(size_t)T_TOK * IEXP];
__device__ int   perm_d[T_TOK];
__device__ int   cnt_d[NEXP];
__device__ int   base_d[NEXP];

// ---------------- routing (single block) ----------------
__global__ void k_route(const int* __restrict__ ids) {
    __shared__ int c[NEXP], b[NEXP], cu[NEXP];
    int t = threadIdx.x;
    if (t < NEXP) { c[t] = 0; cu[t] = 0; }
    __syncthreads();
    for (int i = t; i < T_TOK; i += 256) {
        int v = ids[i]; v = max(0, min(v, VOCAB_SZ - 1));
        atomicAdd(&c[min(v / TPE, NEXP - 1)], 1);
    }
    __syncthreads();
    if (t == 0) { int s = 0; for (int e = 0; e < NEXP; e++) { b[e] = s; s += c[e]; } }
    __syncthreads();
    for (int i = t; i < T_TOK; i += 256) {
        int v = ids[i]; v = max(0, min(v, VOCAB_SZ - 1));
        int e = min(v / TPE, NEXP - 1);
        perm_d[b[e] + atomicAdd(&cu[e], 1)] = i;
    }
    if (t < NEXP) { cnt_d[t] = c[t]; base_d[t] = b[t]; }
}

// ---------------- helpers ----------------
__device__ __forceinline__ unsigned f2t(float f) {
    unsigned u;
    asm("cvt.rna.tf32.f32 %0, %1;" : "=r"(u) : "f"(f));
    return u;
}
__device__ __forceinline__ void mma_t(float* c, const unsigned* a, const unsigned* b) {
    asm volatile(
        "mma.sync.aligned.m16n8k8.row.col.f32.tf32.tf32.f32 "
        "{%0,%1,%2,%3},{%4,%5,%6,%7},{%8,%9},{%0,%1,%2,%3};"
        : "+f"(c[0]), "+f"(c[1]), "+f"(c[2]), "+f"(c[3])
        : "r"(a[0]), "r"(a[1]), "r"(a[2]), "r"(a[3]), "r"(b[0]), "r"(b[1]));
}
__device__ __forceinline__ void cp16(unsigned dst, const float* src) {
    asm volatile("cp.async.cg.shared.global [%0], [%1], 16;" :: "r"(dst), "l"(src));
}
#define CP_COMMIT() asm volatile("cp.async.commit_group;")
#define CP_WAIT1()  asm volatile("cp.async.wait_group 1;")

// ================= fused gate/up + silu =================
// h_scr[perm row] = silu(X@gate[e]) * (X@up[e]) for tile [m0:m0+128, n0:n0+64]
__global__ __launch_bounds__(256, 2)
void k_mlp(const float* __restrict__ X, const float* __restrict__ Gw,
           const float* __restrict__ Uw)
{
    extern __shared__ float sm[];
    int e   = blockIdx.z;
    int cnt = cnt_d[e];
    int m0  = blockIdx.y * BM;
    if (m0 >= cnt) return;
    int n0    = blockIdx.x * BNF;
    int valid = min(cnt - m0, BM);
    int pbase = base_d[e] + m0;
    int tid = threadIdx.x, lane = tid & 31, wid = tid >> 5;

    int* toks = (int*)(sm + SMEMW_F);
    if (tid < BM) toks[tid] = perm_d[pbase + min(tid, valid - 1)];
    __syncthreads();

    // staging assignments
    int ar = tid >> 1, ah = tid & 1;
    const float* Arow = X + (size_t)toks[ar] * HID + ah * 16;
    int bkr = tid >> 3, bnc = (tid & 7) * 8;
    const float* Gr = Gw + (size_t)e * HID * IEXP + (size_t)bkr * IEXP + n0 + bnc;
    const float* Ur = Uw + (size_t)e * HID * IEXP + (size_t)bkr * IEXP + n0 + bnc;

    unsigned sb = (unsigned)__cvta_generic_to_shared(sm);
    unsigned aD = sb + (ar * ASTR + ah * 16) * 4;
    unsigned gD = sb + (AW + bkr * BSTR + bnc) * 4;
    unsigned uD = sb + (AW + BW + bkr * BSTR + bnc) * 4;

    auto stage = [&](int s, int k0) {
        unsigned off = s * (STGW * 4);
        const float* as = Arow + k0;
#pragma unroll
        for (int j = 0; j < 4; j++) cp16(aD + off + j * 16, as + j * 4);
        const float* gs = Gr + (size_t)k0 * IEXP;
        cp16(gD + off, gs); cp16(gD + off + 16, gs + 4);
        const float* us = Ur + (size_t)k0 * IEXP;
        cp16(uD + off, us); cp16(uD + off + 16, us + 4);
    };

    float acc[2][8][4];
#pragma unroll
    for (int i = 0; i < 2; i++)
#pragma unroll
        for (int j = 0; j < 8; j++)
#pragma unroll
            for (int k = 0; k < 4; k++) acc[i][j][k] = 0.f;

    int sel = wid >> 2;          // 0: gate warps, 1: up warps
    int wm  = (wid & 3) * 32;    // warp M offset

    stage(0, 0);  CP_COMMIT();
    stage(1, BK); CP_COMMIT();

    const int nch = HID / BK;    // 64
    int s = 0;
    for (int i = 0; i < nch; i++) {
        CP_WAIT1();
        __syncthreads();
        if (i + 2 < nch) {
            int s2 = s + 2; if (s2 >= NSTAGE) s2 -= NSTAGE;
            stage(s2, (i + 2) * BK);
        }
        CP_COMMIT();

        const float* As = sm + s * STGW;
        const float* Bs = sm + s * STGW + AW + sel * BW;
#pragma unroll
        for (int kk = 0; kk < 4; kk++) {
            unsigned af[2][4];
            int r0 = wm + (lane >> 2);
            int c0 = kk * 8 + (lane & 3);
#pragma unroll
            for (int mi = 0; mi < 2; mi++) {
                af[mi][0] = f2t(As[(r0 + mi * 16) * ASTR + c0]);
                af[mi][1] = f2t(As[(r0 + mi * 16 + 8) * ASTR + c0]);
                af[mi][2] = f2t(As[(r0 + mi * 16) * ASTR + c0 + 4]);
                af[mi][3] = f2t(As[(r0 + mi * 16 + 8) * ASTR + c0 + 4]);
            }
            unsigned bf[8][2];
            int kr = kk * 8 + (lane & 3);
            int nc = lane >> 2;
#pragma unroll
            for (int ni = 0; ni < 8; ni++) {
                bf[ni][0] = f2t(Bs[kr * BSTR + nc + ni * 8]);
                bf[ni][1] = f2t(Bs[(kr + 4) * BSTR + nc + ni * 8]);
            }
#pragma unroll
            for (int mi = 0; mi < 2; mi++)
#pragma unroll
                for (int ni = 0; ni < 8; ni++)
                    mma_t(acc[mi][ni], af[mi], bf[ni]);
        }
        s = (s + 1 == NSTAGE) ? 0 : s + 1;
    }
    __syncthreads();

    // ---- exchange + silu: both groups dump acc to SMEM, then fuse ----
    float* HS = sm + sel * (BM * 68);   // [128][68] each
#pragma unroll
    for (int mi = 0; mi < 2; mi++) {
        int rb = wm + mi * 16 + (lane >> 2);
#pragma unroll
        for (int ni = 0; ni < 8; ni++) {
            int cc = ni * 8 + (lane & 3) * 2;
            HS[rb * 68 + cc]           = acc[mi][ni][0];
            HS[rb * 68 + cc + 1]       = acc[mi][ni][1];
            HS[(rb + 8) * 68 + cc]     = acc[mi][ni][2];
            HS[(rb + 8) * 68 + cc + 1] = acc[mi][ni][3];
        }
    }
    __syncthreads();
    {
        int r = tid >> 1, hf = tid & 1;
        if (r < valid) {
            const float* g = sm + r * 68 + hf * 32;
            const float* u = sm + BM * 68 + r * 68 + hf * 32;
            float* dst = h_scr + (size_t)(pbase + r) * IEXP + n0 + hf * 32;
#pragma unroll
            for (int j = 0; j < 32; j += 4) {
                float4 gv = *(const float4*)(g + j);
                float4 uv = *(const float4*)(u + j);
                float4 h;
                h.x = gv.x / (1.f + __expf(-gv.x)) * uv.x;
                h.y = gv.y / (1.f + __expf(-gv.y)) * uv.y;
                h.z = gv.z / (1.f + __expf(-gv.z)) * uv.z;
                h.w = gv.w / (1.f + __expf(-gv.w)) * uv.w;
                *(float4*)(dst + j) = h;
            }
        }
    }
}

// ================= down-proj with row scatter =================
__global__ __launch_bounds__(256, 2)
void k_down(const float* __restrict__ Dw, float* __restrict__ out)
{
    extern __shared__ float sm[];
    int e   = blockIdx.z;
    int cnt = cnt_d[e];
    int m0  = blockIdx.y * BM;
    if (m0 >= cnt) return;
    int n0    = blockIdx.x * BN3;
    int valid = min(cnt - m0, BM);
    int pbase = base_d[e] + m0;
    int tid = threadIdx.x, lane = tid & 31, wid = tid >> 5;

    int* toks = (int*)(sm + NSTAGE * STG3W);
    if (tid < BM) toks[tid] = perm_d[pbase + min(tid, valid - 1)];
    __syncthreads();

    int ar = tid >> 1, ah = tid & 1;
    int arc = min(ar, valid - 1);
    const float* Arow = h_scr + (size_t)(pbase + arc) * IEXP + ah * 16;
    int bkr = tid >> 1, bnc = (tid & 1) * 64;   // B: 128 floats/row, 2 thr/row, 64 floats each
    const float* Br = Dw + (size_t)e * IEXP * HID + (size_t)bkr * HID + n0 + bnc;

    unsigned sb = (unsigned)__cvta_generic_to_shared(sm);
    unsigned aD = sb + (ar * ASTR + ah * 16) * 4;
    unsigned bD = sb + (AW + (bkr & 31) * B3STR + bnc) * 4;
    int bks = bkr >> 5;  // 0..3: four 32-row segments? no: bkr 0..127 covers 32 rows x ... 

    // fix: B tile is 32 k-rows x 128 n. 256 threads -> 8 thr/row, 16 floats each.
    int b2r = tid >> 3, b2c = (tid & 7) * 16;
    const float* Br2 = Dw + (size_t)e * IEXP * HID + (size_t)b2r * HID + n0 + b2c;
    unsigned bD2 = sb + (AW + b2r * B3STR + b2c) * 4;
    (void)Br; (void)bD; (void)bks;

    auto stage = [&](int s, int k0) {
        unsigned off = s * (STG3W * 4);
        const float* as = Arow + k0;
#pragma unroll
        for (int j = 0; j < 4; j++) cp16(aD + off + j * 16, as + j * 4);
        const float* bs = Br2 + (size_t)k0 * HID;
#pragma unroll
        for (int j = 0; j < 4; j++) cp16(bD2 + off + j * 16, bs + j * 4);
    };

    float acc[2][8][4];
#pragma unroll
    for (int i = 0; i < 2; i++)
#pragma unroll
        for (int j = 0; j < 8; j++)
#pragma unroll
            for (int k = 0; k < 4; k++) acc[i][j][k] = 0.f;

    int wm = (wid >> 1) * 32;
    int wn = (wid & 1) * 64;

    stage(0, 0);  CP_COMMIT();
    stage(1, BK); CP_COMMIT();

    const int nch = IEXP / BK;   // 32
    int s = 0;
    for (int i = 0; i < nch; i++) {
        CP_WAIT1();
        __syncthreads();
        if (i + 2 < nch) {
            int s2 = s + 2; if (s2 >= NSTAGE) s2 -= NSTAGE;
            stage(s2, (i + 2) * BK);
        }
        CP_COMMIT();

        const float* As = sm + s * STG3W;
        const float* Bs = sm + s * STG3W + AW;
#pragma unroll
        for (int kk = 0; kk < 4; kk++) {
            unsigned af[2][4];
            int r0 = wm + (lane >> 2);
            int c0 = kk * 8 + (lane & 3);
#pragma unroll
            for (int mi = 0; mi < 2; mi++) {
                af[mi][0] = f2t(As[(r0 + mi * 16) * ASTR + c0]);
                af[mi][1] = f2t(As[(r0 + mi * 16 + 8) * ASTR + c0]);
                af[mi][2] = f2t(As[(r0 + mi * 16) * ASTR + c0 + 4]);
                af[mi][3] = f2t(As[(r0 + mi * 16 + 8) * ASTR + c0 + 4]);
            }
            unsigned bf[8][2];
            int kr = kk * 8 + (lane & 3);
            int nc = wn + (lane >> 2);
#pragma unroll
            for (int ni = 0; ni < 8; ni++) {
                bf[ni][0] = f2t(Bs[kr * B3STR + nc + ni * 8]);
                bf[ni][1] = f2t(Bs[(kr + 4) * B3STR + nc + ni * 8]);
            }
#pragma unroll
            for (int mi = 0; mi < 2; mi++)
#pragma unroll
                for (int ni = 0; ni < 8; ni++)
                    mma_t(acc[mi][ni], af[mi], bf[ni]);
        }
        s = (s + 1 == NSTAGE) ? 0 : s + 1;
    }

    // direct fragment stores, scattered by token id
#pragma unroll
    for (int mi = 0; mi < 2; mi++) {
        int rb = wm + mi * 16 + (lane >> 2);
#pragma unroll
        for (int ni = 0; ni < 8; ni++) {
            int cc = n0 + wn + ni * 8 + (lane & 3) * 2;
#pragma unroll
            for (int h = 0; h < 2; h++) {
                int r = rb + h * 8;
                if (r < valid) {
                    float* row = out + (size_t)toks[r] * HID;
                    row[cc]     = acc[mi][ni][h * 2];
                    row[cc + 1] = acc[mi][ni][h * 2 + 1];
                }
            }
        }
    }
}

// ---------------- launch ----------------
extern "C" void kernel_launch(void* const* d_in, const int* in_sizes, int n_in,
                              void* d_out, int out_size)
{
    const float* hs   = (const float*)d_in[0];
    const int*   ids  = (const int*)d_in[1];
    const float* gate = (const float*)d_in[2];
    const float* up   = (const float*)d_in[3];
    const float* down = (const float*)d_in[4];
    float*       out  = (float*)d_out;

    cudaFuncSetAttribute(k_mlp,  cudaFuncAttributeMaxDynamicSharedMemorySize, SMEMB_F);
    cudaFuncSetAttribute(k_down, cudaFuncAttributeMaxDynamicSharedMemorySize, SMEMB_3);

    k_route<<<1, 256>>>(ids);
    k_mlp <<<dim3(IEXP / BNF, 32, NEXP), 256, SMEMB_F>>>(hs, gate, up);
    k_down<<<dim3(HID / BN3, 32, NEXP), 256, SMEMB_3>>>(down, out);
}

// round 7
// speedup vs baseline: 1.5679x; 1.0957x over previous
#include <cuda_runtime.h>
#include <cstdint>

#define T_TOK 16384
#define HID   2048
#define IEXP  1024
#define NEXP  8
#define VOCAB_SZ 100000
#define TPE   12500

#define BM 128
#define BK 32
#define ASTR 36
#define AW (BM * ASTR)            // 4608 words
#define BSTRF 132
#define BWF (BK * BSTRF)          // 4224 words
#define STGWF (AW + 2 * BWF)      // 13056 words / stage
#define NST 4
#define SMW_F (NST * STGWF)       // 52224 words
#define SMB_F (SMW_F * 4 + 1024)

#define BSTR3 264
#define BW3 (BK * BSTR3)          // 8448 words
#define STGW3 (AW + BW3)          // 13056 words
#define SMW_3 (NST * STGW3)
#define SMB_3 (SMW_3 * 4 + 1024)

// ---------------- device scratch ----------------
__device__ float x_tf[(size_t)T_TOK * HID];    // tf32-rounded X
__device__ float h_scr[(size_t)T_TOK * IEXP];  // tf32-rounded h
__device__ int   perm_d[T_TOK];
__device__ int   cnt_d[NEXP];
__device__ int   base_d[NEXP];

// ---------------- routing ----------------
__global__ void k_route(const int* __restrict__ ids) {
    __shared__ int c[NEXP], b[NEXP], cu[NEXP];
    int t = threadIdx.x;
    if (t < NEXP) { c[t] = 0; cu[t] = 0; }
    __syncthreads();
    for (int i = t; i < T_TOK; i += 256) {
        int v = ids[i]; v = max(0, min(v, VOCAB_SZ - 1));
        atomicAdd(&c[min(v / TPE, NEXP - 1)], 1);
    }
    __syncthreads();
    if (t == 0) { int s = 0; for (int e = 0; e < NEXP; e++) { b[e] = s; s += c[e]; } }
    __syncthreads();
    for (int i = t; i < T_TOK; i += 256) {
        int v = ids[i]; v = max(0, min(v, VOCAB_SZ - 1));
        int e = min(v / TPE, NEXP - 1);
        perm_d[b[e] + atomicAdd(&cu[e], 1)] = i;
    }
    if (t < NEXP) { cnt_d[t] = c[t]; base_d[t] = b[t]; }
}

// ---------------- helpers ----------------
__device__ __forceinline__ unsigned f2t(float f) {
    unsigned u;
    asm("cvt.rna.tf32.f32 %0, %1;" : "=r"(u) : "f"(f));
    return u;
}
__device__ __forceinline__ void mma_t(float* c, const unsigned* a, const unsigned* b) {
    asm volatile(
        "mma.sync.aligned.m16n8k8.row.col.f32.tf32.tf32.f32 "
        "{%0,%1,%2,%3},{%4,%5,%6,%7},{%8,%9},{%0,%1,%2,%3};"
        : "+f"(c[0]), "+f"(c[1]), "+f"(c[2]), "+f"(c[3])
        : "r"(a[0]), "r"(a[1]), "r"(a[2]), "r"(a[3]), "r"(b[0]), "r"(b[1]));
}
__device__ __forceinline__ void cp16(unsigned dst, const float* src) {
    asm volatile("cp.async.cg.shared.global [%0], [%1], 16;" :: "r"(dst), "l"(src));
}
#define CP_COMMIT() asm volatile("cp.async.commit_group;")
#define CP_WAIT2()  asm volatile("cp.async.wait_group 2;")

// ---------------- pre-round X to tf32 ----------------
__global__ void k_prep(const float* __restrict__ X) {
    size_t i = ((size_t)blockIdx.x * blockDim.x + threadIdx.x) * 4;
    float4 v = *(const float4*)(X + i);
    uint4 w = make_uint4(f2t(v.x), f2t(v.y), f2t(v.z), f2t(v.w));
    *(uint4*)(x_tf + i) = w;
}

// ================= fused gate/up + silu (CTA tile 128 x (128g+128u)) =========
__global__ __launch_bounds__(512, 1)
void k_mlp(const float* __restrict__ Gw, const float* __restrict__ Uw)
{
    extern __shared__ float sm[];
    int e   = blockIdx.z;
    int cnt = cnt_d[e];
    int m0  = blockIdx.y * BM;
    if (m0 >= cnt) return;
    int n0    = blockIdx.x * 128;
    int valid = min(cnt - m0, BM);
    int pbase = base_d[e] + m0;
    int tid = threadIdx.x, lane = tid & 31, wid = tid >> 5;

    int* toks = (int*)(sm + SMW_F);
    if (tid < BM) toks[tid] = perm_d[pbase + min(tid, valid - 1)];
    __syncthreads();

    // A staging (cp.async, pre-rounded): 4 thr/row, 8 floats each
    int ar = tid >> 2, ac = (tid & 3) * 8;
    const float* Arow = x_tf + (size_t)toks[ar] * HID + ac;
    unsigned sb = (unsigned)__cvta_generic_to_shared(sm);
    unsigned aD = sb + (ar * ASTR + ac) * 4;

    // B staging (LDG + cvt + STS): threads 0-255 gate, 256-511 up
    int bt = tid & 255, bsel = tid >> 8;
    int brow = bt >> 5, bc = (bt & 31) * 4;
    const float* Wbase = (bsel ? Uw : Gw) + (size_t)e * HID * IEXP
                       + (size_t)brow * IEXP + n0 + bc;
    unsigned bD = sb + (AW + bsel * BWF + brow * BSTRF + bc) * 4;

    auto stage = [&](int s, int k0) {
        unsigned off = (unsigned)s * (STGWF * 4);
        cp16(aD + off, Arow + k0);
        cp16(aD + off + 16, Arow + k0 + 4);
#pragma unroll
        for (int j = 0; j < 4; j++) {
            float4 v = *(const float4*)(Wbase + (size_t)(k0 + 8 * j) * IEXP);
            uint4 w = make_uint4(f2t(v.x), f2t(v.y), f2t(v.z), f2t(v.w));
            *(uint4*)((char*)sm + (bD - sb) + off + j * (8 * BSTRF * 4)) = w;
        }
    };

    float acc[2][8][4];
#pragma unroll
    for (int i = 0; i < 2; i++)
#pragma unroll
        for (int j = 0; j < 8; j++)
#pragma unroll
            for (int k = 0; k < 4; k++) acc[i][j][k] = 0.f;

    int sel = wid >> 3;                 // 0: gate warps, 1: up warps
    int w8  = wid & 7;
    int wm  = (w8 & 3) * 32;            // 4 M-tiles
    int wn  = (w8 >> 2) * 64;           // 2 N-tiles of 64

    stage(0, 0);       CP_COMMIT();
    stage(1, BK);      CP_COMMIT();
    stage(2, 2 * BK);  CP_COMMIT();

    const int nch = HID / BK;           // 64
    int s = 0;
    for (int i = 0; i < nch; i++) {
        CP_WAIT2();
        __syncthreads();
        if (i + 3 < nch) {
            int s3 = s + 3; if (s3 >= NST) s3 -= NST;
            stage(s3, (i + 3) * BK);
        }
        CP_COMMIT();

        const unsigned* As = (const unsigned*)(sm + s * STGWF);
        const unsigned* Bs = (const unsigned*)(sm + s * STGWF + AW + sel * BWF);
#pragma unroll
        for (int kk = 0; kk < 4; kk++) {
            unsigned af[2][4];
            int r0 = wm + (lane >> 2);
            int c0 = kk * 8 + (lane & 3);
#pragma unroll
            for (int mi = 0; mi < 2; mi++) {
                af[mi][0] = As[(r0 + mi * 16) * ASTR + c0];
                af[mi][1] = As[(r0 + mi * 16 + 8) * ASTR + c0];
                af[mi][2] = As[(r0 + mi * 16) * ASTR + c0 + 4];
                af[mi][3] = As[(r0 + mi * 16 + 8) * ASTR + c0 + 4];
            }
            unsigned bf[8][2];
            int kr = kk * 8 + (lane & 3);
            int nc = wn + (lane >> 2);
#pragma unroll
            for (int ni = 0; ni < 8; ni++) {
                bf[ni][0] = Bs[kr * BSTRF + nc + ni * 8];
                bf[ni][1] = Bs[(kr + 4) * BSTRF + nc + ni * 8];
            }
#pragma unroll
            for (int mi = 0; mi < 2; mi++)
#pragma unroll
                for (int ni = 0; ni < 8; ni++)
                    mma_t(acc[mi][ni], af[mi], bf[ni]);
        }
        s = (s + 1 == NST) ? 0 : s + 1;
    }
    __syncthreads();

    // ---- exchange + silu ----
    float* HS = sm + sel * (BM * BSTRF);   // [128][132] per matrix
#pragma unroll
    for (int mi = 0; mi < 2; mi++) {
        int rb = wm + mi * 16 + (lane >> 2);
#pragma unroll
        for (int ni = 0; ni < 8; ni++) {
            int cc = wn + ni * 8 + (lane & 3) * 2;
            HS[rb * BSTRF + cc]           = acc[mi][ni][0];
            HS[rb * BSTRF + cc + 1]       = acc[mi][ni][1];
            HS[(rb + 8) * BSTRF + cc]     = acc[mi][ni][2];
            HS[(rb + 8) * BSTRF + cc + 1] = acc[mi][ni][3];
        }
    }
    __syncthreads();
    {
        int r = tid & 127, hf = tid >> 7;       // conflict-free reads
        if (r < valid) {
            const float* g = sm + r * BSTRF + hf * 32;
            const float* u = sm + BM * BSTRF + r * BSTRF + hf * 32;
            float* dst = h_scr + (size_t)(pbase + r) * IEXP + n0 + hf * 32;
#pragma unroll
            for (int j = 0; j < 32; j += 4) {
                float4 gv = *(const float4*)(g + j);
                float4 uv = *(const float4*)(u + j);
                uint4 h;
                h.x = f2t(gv.x / (1.f + __expf(-gv.x)) * uv.x);
                h.y = f2t(gv.y / (1.f + __expf(-gv.y)) * uv.y);
                h.z = f2t(gv.z / (1.f + __expf(-gv.z)) * uv.z);
                h.w = f2t(gv.w / (1.f + __expf(-gv.w)) * uv.w);
                *(uint4*)(dst + j) = h;
            }
        }
    }
}

// ================= down-proj (CTA tile 128 x 256) with row scatter ==========
__global__ __launch_bounds__(512, 1)
void k_down(const float* __restrict__ Dw, float* __restrict__ out)
{
    extern __shared__ float sm[];
    int e   = blockIdx.z;
    int cnt = cnt_d[e];
    int m0  = blockIdx.y * BM;
    if (m0 >= cnt) return;
    int n0    = blockIdx.x * 256;
    int valid = min(cnt - m0, BM);
    int pbase = base_d[e] + m0;
    int tid = threadIdx.x, lane = tid & 31, wid = tid >> 5;

    int* toks = (int*)(sm + SMW_3);
    if (tid < BM) toks[tid] = perm_d[pbase + min(tid, valid - 1)];
    __syncthreads();

    int ar = tid >> 2, ac = (tid & 3) * 8;
    const float* Arow = h_scr + (size_t)(pbase + min(ar, valid - 1)) * IEXP + ac;
    unsigned sb = (unsigned)__cvta_generic_to_shared(sm);
    unsigned aD = sb + (ar * ASTR + ac) * 4;

    // B: 32 rows x 256 fl, 64 thr/row, 4 fl each, 4 passes
    int brow = tid >> 6, bc = (tid & 63) * 4;
    const float* Wbase = Dw + (size_t)e * IEXP * HID + (size_t)brow * HID + n0 + bc;
    unsigned bD = sb + (AW + brow * BSTR3 + bc) * 4;

    auto stage = [&](int s, int k0) {
        unsigned off = (unsigned)s * (STGW3 * 4);
        cp16(aD + off, Arow + k0);
        cp16(aD + off + 16, Arow + k0 + 4);
#pragma unroll
        for (int j = 0; j < 4; j++) {
            float4 v = *(const float4*)(Wbase + (size_t)(k0 + 8 * j) * HID);
            uint4 w = make_uint4(f2t(v.x), f2t(v.y), f2t(v.z), f2t(v.w));
            *(uint4*)((char*)sm + (bD - sb) + off + j * (8 * BSTR3 * 4)) = w;
        }
    };

    float acc[2][8][4];
#pragma unroll
    for (int i = 0; i < 2; i++)
#pragma unroll
        for (int j = 0; j < 8; j++)
#pragma unroll
            for (int k = 0; k < 4; k++) acc[i][j][k] = 0.f;

    int wm = (wid & 3) * 32;
    int wn = (wid >> 2) * 64;           // 4 N-tiles of 64

    stage(0, 0);       CP_COMMIT();
    stage(1, BK);      CP_COMMIT();
    stage(2, 2 * BK);  CP_COMMIT();

    const int nch = IEXP / BK;          // 32
    int s = 0;
    for (int i = 0; i < nch; i++) {
        CP_WAIT2();
        __syncthreads();
        if (i + 3 < nch) {
            int s3 = s + 3; if (s3 >= NST) s3 -= NST;
            stage(s3, (i + 3) * BK);
        }
        CP_COMMIT();

        const unsigned* As = (const unsigned*)(sm + s * STGW3);
        const unsigned* Bs = (const unsigned*)(sm + s * STGW3 + AW);
#pragma unroll
        for (int kk = 0; kk < 4; kk++) {
            unsigned af[2][4];
            int r0 = wm + (lane >> 2);
            int c0 = kk * 8 + (lane & 3);
#pragma unroll
            for (int mi = 0; mi < 2; mi++) {
                af[mi][0] = As[(r0 + mi * 16) * ASTR + c0];
                af[mi][1] = As[(r0 + mi * 16 + 8) * ASTR + c0];
                af[mi][2] = As[(r0 + mi * 16) * ASTR + c0 + 4];
                af[mi][3] = As[(r0 + mi * 16 + 8) * ASTR + c0 + 4];
            }
            unsigned bf[8][2];
            int kr = kk * 8 + (lane & 3);
            int nc = wn + (lane >> 2);
#pragma unroll
            for (int ni = 0; ni < 8; ni++) {
                bf[ni][0] = Bs[kr * BSTR3 + nc + ni * 8];
                bf[ni][1] = Bs[(kr + 4) * BSTR3 + nc + ni * 8];
            }
#pragma unroll
            for (int mi = 0; mi < 2; mi++)
#pragma unroll
                for (int ni = 0; ni < 8; ni++)
                    mma_t(acc[mi][ni], af[mi], bf[ni]);
        }
        s = (s + 1 == NST) ? 0 : s + 1;
    }

    // scatter rows by token id
#pragma unroll
    for (int mi = 0; mi < 2; mi++) {
        int rb = wm + mi * 16 + (lane >> 2);
#pragma unroll
        for (int ni = 0; ni < 8; ni++) {
            int cc = n0 + wn + ni * 8 + (lane & 3) * 2;
#pragma unroll
            for (int h = 0; h < 2; h++) {
                int r = rb + h * 8;
                if (r < valid) {
                    float* row = out + (size_t)toks[r] * HID;
                    row[cc]     = acc[mi][ni][h * 2];
                    row[cc + 1] = acc[mi][ni][h * 2 + 1];
                }
            }
        }
    }
}

// ---------------- launch ----------------
extern "C" void kernel_launch(void* const* d_in, const int* in_sizes, int n_in,
                              void* d_out, int out_size)
{
    const float* hs   = (const float*)d_in[0];
    const int*   ids  = (const int*)d_in[1];
    const float* gate = (const float*)d_in[2];
    const float* up   = (const float*)d_in[3];
    const float* down = (const float*)d_in[4];
    float*       out  = (float*)d_out;

    cudaFuncSetAttribute(k_mlp,  cudaFuncAttributeMaxDynamicSharedMemorySize, SMB_F);
    cudaFuncSetAttribute(k_down, cudaFuncAttributeMaxDynamicSharedMemorySize, SMB_3);

    k_route<<<1, 256>>>(ids);
    k_prep<<<(T_TOK * HID) / 1024, 256>>>(hs);
    k_mlp <<<dim3(IEXP / 128, 32, NEXP), 512, SMB_F>>>(gate, up);
    k_down<<<dim3(HID / 256, 32, NEXP), 512, SMB_3>>>(down, out);
}

// round 8
// speedup vs baseline: 1.6561x; 1.0563x over previous
#include <cuda_runtime.h>
#include <cstdint>

#define T_TOK 16384
#define HID   2048
#define IEXP  1024
#define NEXP  8
#define VOCAB_SZ 100000
#define TPE   12500

#define BM 128
#define BK 32
#define STR 36                     // smem row stride (words); 36%8==4 -> ldmatrix conflict-free
#define AW (BM * STR)              // 4608 words
#define BROWS 256                  // B n-rows per stage (fused: 128 gate + 128 up; down: 256)
#define BWW (BROWS * STR)          // 9216 words
#define STGW (AW + BWW)            // 13824 words / stage
#define NST 4
#define SMW (NST * STGW)           // 55296 words
#define SMB (SMW * 4 + 1024)       // ~222 KB

// ---------------- device scratch ----------------
__device__ float x_tf[(size_t)T_TOK * HID];            // tf32-rounded X
__device__ float h_scr[(size_t)T_TOK * IEXP];          // tf32-rounded h
__device__ float gt_w[(size_t)NEXP * IEXP * HID];      // gate^T  [e][n][k]
__device__ float ut_w[(size_t)NEXP * IEXP * HID];      // up^T    [e][n][k]
__device__ float dt_w[(size_t)NEXP * HID * IEXP];      // down^T  [e][n][k]
__device__ int   perm_d[T_TOK];
__device__ int   cnt_d[NEXP];
__device__ int   base_d[NEXP];

// ---------------- routing ----------------
__global__ void k_route(const int* __restrict__ ids) {
    __shared__ int c[NEXP], b[NEXP], cu[NEXP];
    int t = threadIdx.x;
    if (t < NEXP) { c[t] = 0; cu[t] = 0; }
    __syncthreads();
    for (int i = t; i < T_TOK; i += 256) {
        int v = ids[i]; v = max(0, min(v, VOCAB_SZ - 1));
        atomicAdd(&c[min(v / TPE, NEXP - 1)], 1);
    }
    __syncthreads();
    if (t == 0) { int s = 0; for (int e = 0; e < NEXP; e++) { b[e] = s; s += c[e]; } }
    __syncthreads();
    for (int i = t; i < T_TOK; i += 256) {
        int v = ids[i]; v = max(0, min(v, VOCAB_SZ - 1));
        int e = min(v / TPE, NEXP - 1);
        perm_d[b[e] + atomicAdd(&cu[e], 1)] = i;
    }
    if (t < NEXP) { cnt_d[t] = c[t]; base_d[t] = b[t]; }
}

// ---------------- helpers ----------------
__device__ __forceinline__ unsigned f2t(float f) {
    unsigned u;
    asm("cvt.rna.tf32.f32 %0, %1;" : "=r"(u) : "f"(f));
    return u;
}
__device__ __forceinline__ void mma_t(float* c, const unsigned* a, const unsigned* b) {
    asm volatile(
        "mma.sync.aligned.m16n8k8.row.col.f32.tf32.tf32.f32 "
        "{%0,%1,%2,%3},{%4,%5,%6,%7},{%8,%9},{%0,%1,%2,%3};"
        : "+f"(c[0]), "+f"(c[1]), "+f"(c[2]), "+f"(c[3])
        : "r"(a[0]), "r"(a[1]), "r"(a[2]), "r"(a[3]), "r"(b[0]), "r"(b[1]));
}
__device__ __forceinline__ void cp16(unsigned dst, const float* src) {
    asm volatile("cp.async.cg.shared.global [%0], [%1], 16;" :: "r"(dst), "l"(src));
}
#define CP_COMMIT() asm volatile("cp.async.commit_group;")
#define CP_WAIT2()  asm volatile("cp.async.wait_group 2;")
#define LDSM4(r0, r1, r2, r3, addr)                                            \
    asm volatile("ldmatrix.sync.aligned.m8n8.x4.shared.b16 {%0,%1,%2,%3}, [%4];" \
        : "=r"(r0), "=r"(r1), "=r"(r2), "=r"(r3) : "r"(addr))

// ---------------- pre-round X ----------------
__global__ void k_prep(const float* __restrict__ X) {
    size_t i = ((size_t)blockIdx.x * blockDim.x + threadIdx.x) * 4;
    float4 v = *(const float4*)(X + i);
    uint4 w = make_uint4(f2t(v.x), f2t(v.y), f2t(v.z), f2t(v.w));
    *(uint4*)(x_tf + i) = w;
}

// ---------------- transpose + round weights: Wt[e][n][k] = rnd(W[e][k][n]) ----
__global__ void k_tw(const float* __restrict__ W, float* __restrict__ Wt,
                     int K, int N) {
    __shared__ float tile[32][33];
    int e = blockIdx.z;
    int n0 = blockIdx.x * 32, k0 = blockIdx.y * 32;
    const float* Wp = W + (size_t)e * K * N;
    float* Wq = Wt + (size_t)e * K * N;
    int tx = threadIdx.x, ty = threadIdx.y;   // 32 x 8
#pragma unroll
    for (int j = 0; j < 32; j += 8)
        tile[ty + j][tx] = Wp[(size_t)(k0 + ty + j) * N + n0 + tx];
    __syncthreads();
#pragma unroll
    for (int j = 0; j < 32; j += 8)
        Wq[(size_t)(n0 + ty + j) * K + k0 + tx] = __uint_as_float(f2t(tile[tx][ty + j]));
}

// ================= fused gate/up + silu (CTA 128m x (128g+128u)) =============
__global__ __launch_bounds__(512, 1)
void k_mlp()
{
    extern __shared__ float sm[];
    int e   = blockIdx.z;
    int cnt = cnt_d[e];
    int m0  = blockIdx.y * BM;
    if (m0 >= cnt) return;
    int n0    = blockIdx.x * 128;
    int valid = min(cnt - m0, BM);
    int pbase = base_d[e] + m0;
    int tid = threadIdx.x, lane = tid & 31, wid = tid >> 5;

    int* toks = (int*)(sm + SMW);
    if (tid < BM) toks[tid] = perm_d[pbase + min(tid, valid - 1)];
    __syncthreads();

    // A staging: 4 thr/row, 8 floats each (2 cp16)
    int ar = tid >> 2, ac = (tid & 3) * 8;
    const float* Arow = x_tf + (size_t)toks[ar] * HID + ac;
    unsigned sb = (unsigned)__cvta_generic_to_shared(sm);
    unsigned aD = sb + (ar * STR + ac) * 4;

    // B staging: 256 n-rows (gate 0-127, up 128-255), 2 thr/row, 16 floats (4 cp16)
    int br = tid >> 1, bc = (tid & 1) * 16;
    const float* Brow = (br < 128)
        ? (gt_w + (size_t)e * IEXP * HID + (size_t)(n0 + br) * HID + bc)
        : (ut_w + (size_t)e * IEXP * HID + (size_t)(n0 + br - 128) * HID + bc);
    unsigned bD = sb + (AW + br * STR + bc) * 4;

    auto stage = [&](int s, int k0) {
        unsigned off = (unsigned)s * (STGW * 4);
        cp16(aD + off,      Arow + k0);
        cp16(aD + off + 16, Arow + k0 + 4);
        const float* bs = Brow + k0;
#pragma unroll
        for (int j = 0; j < 4; j++) cp16(bD + off + j * 16, bs + j * 4);
    };

    float acc[2][8][4];
#pragma unroll
    for (int i = 0; i < 2; i++)
#pragma unroll
        for (int j = 0; j < 8; j++)
#pragma unroll
            for (int k = 0; k < 4; k++) acc[i][j][k] = 0.f;

    int sel = wid >> 3;                 // 0: gate, 1: up
    int w8  = wid & 7;
    int wm  = (w8 & 3) * 32;
    int wn  = (w8 >> 2) * 64;

    // ldmatrix per-thread base addresses (bytes)
    unsigned aLd = sb + ((wm + (lane & 7) + ((lane >> 3) & 1) * 8) * STR
                         + ((lane >> 4) & 1) * 4) * 4;
    unsigned bLd = sb + (AW + (sel * 128 + wn + (lane & 7) + ((lane >> 4) & 1) * 8) * STR
                         + ((lane >> 3) & 1) * 4) * 4;

    stage(0, 0);       CP_COMMIT();
    stage(1, BK);      CP_COMMIT();
    stage(2, 2 * BK);  CP_COMMIT();

    const int nch = HID / BK;           // 64
    int s = 0;
    for (int i = 0; i < nch; i++) {
        CP_WAIT2();
        __syncthreads();
        if (i + 3 < nch) {
            int s3 = s + 3; if (s3 >= NST) s3 -= NST;
            stage(s3, (i + 3) * BK);
        }
        CP_COMMIT();

        unsigned stOff = (unsigned)s * (STGW * 4);
#pragma unroll
        for (int kk = 0; kk < 4; kk++) {
            unsigned af[2][4];
#pragma unroll
            for (int mi = 0; mi < 2; mi++)
                LDSM4(af[mi][0], af[mi][1], af[mi][2], af[mi][3],
                      aLd + stOff + mi * (16 * STR * 4) + kk * 32);
#pragma unroll
            for (int p = 0; p < 4; p++) {
                unsigned b0, b1, b2, b3;
                LDSM4(b0, b1, b2, b3, bLd + stOff + p * (16 * STR * 4) + kk * 32);
                unsigned bf0[2] = { b0, b1 }, bf1[2] = { b2, b3 };
#pragma unroll
                for (int mi = 0; mi < 2; mi++) {
                    mma_t(acc[mi][2 * p],     af[mi], bf0);
                    mma_t(acc[mi][2 * p + 1], af[mi], bf1);
                }
            }
        }
        s = (s + 1 == NST) ? 0 : s + 1;
    }
    __syncthreads();

    // ---- exchange + silu ----
    float* HS = sm + sel * (BM * 132);
#pragma unroll
    for (int mi = 0; mi < 2; mi++) {
        int rb = wm + mi * 16 + (lane >> 2);
#pragma unroll
        for (int ni = 0; ni < 8; ni++) {
            int cc = wn + ni * 8 + (lane & 3) * 2;
            HS[rb * 132 + cc]           = acc[mi][ni][0];
            HS[rb * 132 + cc + 1]       = acc[mi][ni][1];
            HS[(rb + 8) * 132 + cc]     = acc[mi][ni][2];
            HS[(rb + 8) * 132 + cc + 1] = acc[mi][ni][3];
        }
    }
    __syncthreads();
    {
        int r = tid & 127, hf = tid >> 7;
        if (r < valid) {
            const float* g = sm + r * 132 + hf * 32;
            const float* u = sm + BM * 132 + r * 132 + hf * 32;
            float* dst = h_scr + (size_t)(pbase + r) * IEXP + n0 + hf * 32;
#pragma unroll
            for (int j = 0; j < 32; j += 4) {
                float4 gv = *(const float4*)(g + j);
                float4 uv = *(const float4*)(u + j);
                uint4 h;
                h.x = f2t(gv.x / (1.f + __expf(-gv.x)) * uv.x);
                h.y = f2t(gv.y / (1.f + __expf(-gv.y)) * uv.y);
                h.z = f2t(gv.z / (1.f + __expf(-gv.z)) * uv.z);
                h.w = f2t(gv.w / (1.f + __expf(-gv.w)) * uv.w);
                *(uint4*)(dst + j) = h;
            }
        }
    }
}

// ================= down-proj (CTA 128m x 256n) with row scatter ==============
__global__ __launch_bounds__(512, 1)
void k_down(float* __restrict__ out)
{
    extern __shared__ float sm[];
    int e   = blockIdx.z;
    int cnt = cnt_d[e];
    int m0  = blockIdx.y * BM;
    if (m0 >= cnt) return;
    int n0    = blockIdx.x * 256;
    int valid = min(cnt - m0, BM);
    int pbase = base_d[e] + m0;
    int tid = threadIdx.x, lane = tid & 31, wid = tid >> 5;

    int* toks = (int*)(sm + SMW);
    if (tid < BM) toks[tid] = perm_d[pbase + min(tid, valid - 1)];
    __syncthreads();

    int ar = tid >> 2, ac = (tid & 3) * 8;
    const float* Arow = h_scr + (size_t)(pbase + min(ar, valid - 1)) * IEXP + ac;
    unsigned sb = (unsigned)__cvta_generic_to_shared(sm);
    unsigned aD = sb + (ar * STR + ac) * 4;

    int br = tid >> 1, bc = (tid & 1) * 16;
    const float* Brow = dt_w + (size_t)e * HID * IEXP + (size_t)(n0 + br) * IEXP + bc;
    unsigned bD = sb + (AW + br * STR + bc) * 4;

    auto stage = [&](int s, int k0) {
        unsigned off = (unsigned)s * (STGW * 4);
        cp16(aD + off,      Arow + k0);
        cp16(aD + off + 16, Arow + k0 + 4);
        const float* bs = Brow + k0;
#pragma unroll
        for (int j = 0; j < 4; j++) cp16(bD + off + j * 16, bs + j * 4);
    };

    float acc[2][8][4];
#pragma unroll
    for (int i = 0; i < 2; i++)
#pragma unroll
        for (int j = 0; j < 8; j++)
#pragma unroll
            for (int k = 0; k < 4; k++) acc[i][j][k] = 0.f;

    int wm = (wid & 3) * 32;
    int wn = (wid >> 2) * 64;           // 4 x 64 over 256 n

    unsigned aLd = sb + ((wm + (lane & 7) + ((lane >> 3) & 1) * 8) * STR
                         + ((lane >> 4) & 1) * 4) * 4;
    unsigned bLd = sb + (AW + (wn + (lane & 7) + ((lane >> 4) & 1) * 8) * STR
                         + ((lane >> 3) & 1) * 4) * 4;

    stage(0, 0);       CP_COMMIT();
    stage(1, BK);      CP_COMMIT();
    stage(2, 2 * BK);  CP_COMMIT();

    const int nch = IEXP / BK;          // 32
    int s = 0;
    for (int i = 0; i < nch; i++) {
        CP_WAIT2();
        __syncthreads();
        if (i + 3 < nch) {
            int s3 = s + 3; if (s3 >= NST) s3 -= NST;
            stage(s3, (i + 3) * BK);
        }
        CP_COMMIT();

        unsigned stOff = (unsigned)s * (STGW * 4);
#pragma unroll
        for (int kk = 0; kk < 4; kk++) {
            unsigned af[2][4];
#pragma unroll
            for (int mi = 0; mi < 2; mi++)
                LDSM4(af[mi][0], af[mi][1], af[mi][2], af[mi][3],
                      aLd + stOff + mi * (16 * STR * 4) + kk * 32);
#pragma unroll
            for (int p = 0; p < 4; p++) {
                unsigned b0, b1, b2, b3;
                LDSM4(b0, b1, b2, b3, bLd + stOff + p * (16 * STR * 4) + kk * 32);
                unsigned bf0[2] = { b0, b1 }, bf1[2] = { b2, b3 };
#pragma unroll
                for (int mi = 0; mi < 2; mi++) {
                    mma_t(acc[mi][2 * p],     af[mi], bf0);
                    mma_t(acc[mi][2 * p + 1], af[mi], bf1);
                }
            }
        }
        s = (s + 1 == NST) ? 0 : s + 1;
    }

    // scatter rows by token id
#pragma unroll
    for (int mi = 0; mi < 2; mi++) {
        int rb = wm + mi * 16 + (lane >> 2);
#pragma unroll
        for (int ni = 0; ni < 8; ni++) {
            int cc = n0 + wn + ni * 8 + (lane & 3) * 2;
#pragma unroll
            for (int h = 0; h < 2; h++) {
                int r = rb + h * 8;
                if (r < valid) {
                    float* row = out + (size_t)toks[r] * HID;
                    row[cc]     = acc[mi][ni][h * 2];
                    row[cc + 1] = acc[mi][ni][h * 2 + 1];
                }
            }
        }
    }
}

// ---------------- launch ----------------
extern "C" void kernel_launch(void* const* d_in, const int* in_sizes, int n_in,
                              void* d_out, int out_size)
{
    const float* hs   = (const float*)d_in[0];
    const int*   ids  = (const int*)d_in[1];
    const float* gate = (const float*)d_in[2];
    const float* up   = (const float*)d_in[3];
    const float* down = (const float*)d_in[4];
    float*       out  = (float*)d_out;

    cudaFuncSetAttribute(k_mlp,  cudaFuncAttributeMaxDynamicSharedMemorySize, SMB);
    cudaFuncSetAttribute(k_down, cudaFuncAttributeMaxDynamicSharedMemorySize, SMB);

    float* gt; cudaGetSymbolAddress((void**)&gt, gt_w);
    float* ut; cudaGetSymbolAddress((void**)&ut, ut_w);
    float* dt; cudaGetSymbolAddress((void**)&dt, dt_w);

    k_route<<<1, 256>>>(ids);
    k_prep<<<(T_TOK * HID) / 1024, 256>>>(hs);
    k_tw<<<dim3(IEXP / 32, HID / 32, NEXP), dim3(32, 8)>>>(gate, gt, HID, IEXP);
    k_tw<<<dim3(IEXP / 32, HID / 32, NEXP), dim3(32, 8)>>>(up,   ut, HID, IEXP);
    k_tw<<<dim3(HID / 32, IEXP / 32, NEXP), dim3(32, 8)>>>(down, dt, IEXP, HID);
    k_mlp <<<dim3(IEXP / 128, 32, NEXP), 512, SMB>>>();
    k_down<<<dim3(HID / 256, 32, NEXP), 512, SMB>>>(out);
}

// round 10
// speedup vs baseline: 3.5376x; 2.1361x over previous
#include <cuda_runtime.h>
#include <cuda_fp16.h>
#include <cstdint>

#define T_TOK 16384
#define HID   2048
#define IEXP  1024
#define NEXP  8
#define VOCAB_SZ 100000
#define TPE   12500

#define BM 128
#define BK 32
#define STRA 40                       // A smem row stride (halfs): 80B -> 16B aligned, bank-conflict-free
#define AH (BM * STRA)                // 5120 halfs / stage

// fused kernel B: 2 matrices x 32 k-rows x (64+8) halfs
#define BSTRF 72
#define BHF (2 * BK * BSTRF)          // 4608 halfs
#define STGH_F (AH + BHF)             // 9728 halfs
#define NST 4
#define SMB_F (NST * STGH_F * 2 + 576)

// down kernel B: 32 k-rows x (128+8) halfs
#define BSTRD 136
#define BHD (BK * BSTRD)              // 4352 halfs
#define STGH_D (AH + BHD)             // 9472 halfs
#define SMB_D (NST * STGH_D * 2 + 576)

// ---------------- device scratch ----------------
__device__ __half x_h [(size_t)T_TOK * HID];
__device__ __half h_h [(size_t)T_TOK * IEXP];
__device__ __half gw_h[(size_t)NEXP * HID * IEXP];   // [e][k][n] half
__device__ __half uw_h[(size_t)NEXP * HID * IEXP];
__device__ __half dw_h[(size_t)NEXP * IEXP * HID];
__device__ int    perm_d[T_TOK];
__device__ int    cnt_d[NEXP];
__device__ int    base_d[NEXP];

// ---------------- routing ----------------
__global__ void k_route(const int* __restrict__ ids) {
    __shared__ int c[NEXP], b[NEXP], cu[NEXP];
    int t = threadIdx.x;
    if (t < NEXP) { c[t] = 0; cu[t] = 0; }
    __syncthreads();
    for (int i = t; i < T_TOK; i += 256) {
        int v = ids[i]; v = max(0, min(v, VOCAB_SZ - 1));
        atomicAdd(&c[min(v / TPE, NEXP - 1)], 1);
    }
    __syncthreads();
    if (t == 0) { int s = 0; for (int e = 0; e < NEXP; e++) { b[e] = s; s += c[e]; } }
    __syncthreads();
    for (int i = t; i < T_TOK; i += 256) {
        int v = ids[i]; v = max(0, min(v, VOCAB_SZ - 1));
        int e = min(v / TPE, NEXP - 1);
        perm_d[b[e] + atomicAdd(&cu[e], 1)] = i;
    }
    if (t < NEXP) { cnt_d[t] = c[t]; base_d[t] = b[t]; }
}

// ---------------- conversions ----------------
__global__ void k_prep(const float* __restrict__ X) {
    size_t i = ((size_t)blockIdx.x * blockDim.x + threadIdx.x) * 8;
    float4 v0 = *(const float4*)(X + i);
    float4 v1 = *(const float4*)(X + i + 4);
    __half2 h0 = __floats2half2_rn(v0.x, v0.y), h1 = __floats2half2_rn(v0.z, v0.w);
    __half2 h2 = __floats2half2_rn(v1.x, v1.y), h3 = __floats2half2_rn(v1.z, v1.w);
    uint4 w = make_uint4(*(unsigned*)&h0, *(unsigned*)&h1, *(unsigned*)&h2, *(unsigned*)&h3);
    *(uint4*)(x_h + i) = w;
}

__global__ void k_wconv(const float* __restrict__ G, const float* __restrict__ U,
                        const float* __restrict__ D) {
    const float* src = (blockIdx.y == 0) ? G : (blockIdx.y == 1) ? U : D;
    __half* dst = (blockIdx.y == 0) ? gw_h : (blockIdx.y == 1) ? uw_h : dw_h;
    size_t i = ((size_t)blockIdx.x * blockDim.x + threadIdx.x) * 8;
    float4 v0 = *(const float4*)(src + i);
    float4 v1 = *(const float4*)(src + i + 4);
    __half2 h0 = __floats2half2_rn(v0.x, v0.y), h1 = __floats2half2_rn(v0.z, v0.w);
    __half2 h2 = __floats2half2_rn(v1.x, v1.y), h3 = __floats2half2_rn(v1.z, v1.w);
    uint4 w = make_uint4(*(unsigned*)&h0, *(unsigned*)&h1, *(unsigned*)&h2, *(unsigned*)&h3);
    *(uint4*)(dst + i) = w;
}

// ---------------- helpers ----------------
__device__ __forceinline__ void mma_h(float* c, const unsigned* a, const unsigned* b) {
    asm volatile(
        "mma.sync.aligned.m16n8k16.row.col.f32.f16.f16.f32 "
        "{%0,%1,%2,%3},{%4,%5,%6,%7},{%8,%9},{%0,%1,%2,%3};"
        : "+f"(c[0]), "+f"(c[1]), "+f"(c[2]), "+f"(c[3])
        : "r"(a[0]), "r"(a[1]), "r"(a[2]), "r"(a[3]), "r"(b[0]), "r"(b[1]));
}
__device__ __forceinline__ void cp16(unsigned dst, const void* src) {
    asm volatile("cp.async.cg.shared.global [%0], [%1], 16;" :: "r"(dst), "l"(src));
}
#define CP_COMMIT() asm volatile("cp.async.commit_group;")
#define CP_WAIT2()  asm volatile("cp.async.wait_group 2;")
#define LDSM4(r0, r1, r2, r3, addr)                                             \
    asm volatile("ldmatrix.sync.aligned.m8n8.x4.shared.b16 {%0,%1,%2,%3}, [%4];" \
        : "=r"(r0), "=r"(r1), "=r"(r2), "=r"(r3) : "r"(addr))
#define LDSM4T(r0, r1, r2, r3, addr)                                            \
    asm volatile("ldmatrix.sync.aligned.m8n8.x4.trans.shared.b16 {%0,%1,%2,%3}, [%4];" \
        : "=r"(r0), "=r"(r1), "=r"(r2), "=r"(r3) : "r"(addr))

// ================= fused gate/up + silu (CTA 128m x 64n, both matrices) =====
__global__ __launch_bounds__(256, 2)
void k_mlp()
{
    extern __shared__ __half smh[];
    int e   = blockIdx.z;
    int cnt = cnt_d[e];
    int m0  = blockIdx.y * BM;
    if (m0 >= cnt) return;
    int n0    = blockIdx.x * 64;
    int valid = min(cnt - m0, BM);
    int pbase = base_d[e] + m0;
    int tid = threadIdx.x, lane = tid & 31, wid = tid >> 5;

    int* toks = (int*)(smh + NST * STGH_F);
    if (tid < BM) toks[tid] = perm_d[pbase + min(tid, valid - 1)];
    __syncthreads();

    // A staging: 2 thr/row, 16 halfs (32B) each
    int arow = tid >> 1, aseg = tid & 1;
    const __half* Ag = x_h + (size_t)toks[arow] * HID + aseg * 16;
    unsigned sb = (unsigned)__cvta_generic_to_shared(smh);
    unsigned aD = sb + (arow * STRA + aseg * 16) * 2;

    // B staging: [k][n] half; 32 k-rows x 64 halfs per matrix; 8 thr/row x 16B
    int brow = tid >> 3, bslot = tid & 7;
    const __half* Gg = gw_h + (size_t)e * HID * IEXP + (size_t)brow * IEXP + n0 + bslot * 8;
    const __half* Ug = uw_h + (size_t)e * HID * IEXP + (size_t)brow * IEXP + n0 + bslot * 8;
    unsigned gD = sb + (AH + brow * BSTRF + bslot * 8) * 2;
    unsigned uD = sb + (AH + BK * BSTRF + brow * BSTRF + bslot * 8) * 2;

    auto stage = [&](int s, int k0) {
        unsigned off = (unsigned)s * (STGH_F * 2);
        cp16(aD + off,      Ag + k0);
        cp16(aD + off + 16, Ag + k0 + 8);
        cp16(gD + off, Gg + (size_t)k0 * IEXP);
        cp16(uD + off, Ug + (size_t)k0 * IEXP);
    };

    float acc[2][8][4];
#pragma unroll
    for (int i = 0; i < 2; i++)
#pragma unroll
        for (int j = 0; j < 8; j++)
#pragma unroll
            for (int k = 0; k < 4; k++) acc[i][j][k] = 0.f;

    int sel = wid >> 2;                  // 0: gate, 1: up
    int wm  = (wid & 3) * 32;

    unsigned aLd = sb + ((wm + (lane & 7) + ((lane >> 3) & 1) * 8) * STRA
                         + ((lane >> 4) & 1) * 8) * 2;
    unsigned bLd = sb + (AH + sel * (BK * BSTRF)
                         + ((lane & 7) + ((lane >> 3) & 1) * 8) * BSTRF
                         + ((lane >> 4) & 1) * 8) * 2;

    stage(0, 0);       CP_COMMIT();
    stage(1, BK);      CP_COMMIT();
    stage(2, 2 * BK);  CP_COMMIT();

    const int nch = HID / BK;            // 64
    int s = 0;
    for (int i = 0; i < nch; i++) {
        CP_WAIT2();
        __syncthreads();
        if (i + 3 < nch) {
            int s3 = s + 3; if (s3 >= NST) s3 -= NST;
            stage(s3, (i + 3) * BK);
        }
        CP_COMMIT();

        unsigned stOff = (unsigned)s * (STGH_F * 2);
#pragma unroll
        for (int kk = 0; kk < 2; kk++) {
            unsigned af[2][4];
#pragma unroll
            for (int mi = 0; mi < 2; mi++)
                LDSM4(af[mi][0], af[mi][1], af[mi][2], af[mi][3],
                      aLd + stOff + mi * (16 * STRA * 2) + kk * 32);
#pragma unroll
            for (int p = 0; p < 4; p++) {
                unsigned b0, b1, b2, b3;
                LDSM4T(b0, b1, b2, b3,
                       bLd + stOff + kk * (16 * BSTRF * 2) + p * 32);
                unsigned bf0[2] = { b0, b1 }, bf1[2] = { b2, b3 };
#pragma unroll
                for (int mi = 0; mi < 2; mi++) {
                    mma_h(acc[mi][2 * p],     af[mi], bf0);
                    mma_h(acc[mi][2 * p + 1], af[mi], bf1);
                }
            }
        }
        s = (s + 1 == NST) ? 0 : s + 1;
    }
    __syncthreads();

    // ---- exchange + silu: gate/up accs -> smem fp32, combine, store half ----
    float* HS = (float*)smh + sel * (BM * 68);
#pragma unroll
    for (int mi = 0; mi < 2; mi++) {
        int rb = wm + mi * 16 + (lane >> 2);
#pragma unroll
        for (int ni = 0; ni < 8; ni++) {
            int cc = ni * 8 + (lane & 3) * 2;
            HS[rb * 68 + cc]           = acc[mi][ni][0];
            HS[rb * 68 + cc + 1]       = acc[mi][ni][1];
            HS[(rb + 8) * 68 + cc]     = acc[mi][ni][2];
            HS[(rb + 8) * 68 + cc + 1] = acc[mi][ni][3];
        }
    }
    __syncthreads();
    {
        int r = tid >> 1, hf = tid & 1;
        if (r < valid) {
            const float* g = (float*)smh + r * 68 + hf * 32;
            const float* u = (float*)smh + BM * 68 + r * 68 + hf * 32;
            __half* dst = h_h + (size_t)(pbase + r) * IEXP + n0 + hf * 32;
#pragma unroll
            for (int j = 0; j < 32; j += 8) {
                float hv[8];
#pragma unroll
                for (int q = 0; q < 8; q++) {
                    float gv = g[j + q], uv = u[j + q];
                    hv[q] = gv / (1.f + __expf(-gv)) * uv;
                }
                __half2 p0 = __floats2half2_rn(hv[0], hv[1]);
                __half2 p1 = __floats2half2_rn(hv[2], hv[3]);
                __half2 p2 = __floats2half2_rn(hv[4], hv[5]);
                __half2 p3 = __floats2half2_rn(hv[6], hv[7]);
                uint4 w = make_uint4(*(unsigned*)&p0, *(unsigned*)&p1,
                                     *(unsigned*)&p2, *(unsigned*)&p3);
                *(uint4*)(dst + j) = w;
            }
        }
    }
}

// ================= down-proj (CTA 128m x 128n) with row scatter ==============
__global__ __launch_bounds__(256, 2)
void k_down(float* __restrict__ out)
{
    extern __shared__ __half smh[];
    int e   = blockIdx.z;
    int cnt = cnt_d[e];
    int m0  = blockIdx.y * BM;
    if (m0 >= cnt) return;
    int n0    = blockIdx.x * 128;
    int valid = min(cnt - m0, BM);
    int pbase = base_d[e] + m0;
    int tid = threadIdx.x, lane = tid & 31, wid = tid >> 5;

    int* toks = (int*)(smh + NST * STGH_D);
    if (tid < BM) toks[tid] = perm_d[pbase + min(tid, valid - 1)];
    __syncthreads();

    int arow = tid >> 1, aseg = tid & 1;
    const __half* Ag = h_h + (size_t)(pbase + min(arow, valid - 1)) * IEXP + aseg * 16;
    unsigned sb = (unsigned)__cvta_generic_to_shared(smh);
    unsigned aD = sb + (arow * STRA + aseg * 16) * 2;

    // B: 32 k-rows x 128 halfs (256B): 16 thr/row x 16B
    int brow = tid >> 4, bslot = tid & 15;
    const __half* Dg = dw_h + (size_t)e * IEXP * HID + (size_t)brow * HID + n0 + bslot * 8;
    unsigned bD = sb + (AH + brow * BSTRD + bslot * 8) * 2;

    auto stage = [&](int s, int k0) {
        unsigned off = (unsigned)s * (STGH_D * 2);
        cp16(aD + off,      Ag + k0);
        cp16(aD + off + 16, Ag + k0 + 8);
        cp16(bD + off, Dg + (size_t)k0 * HID);
        cp16(bD + off + (16 * BSTRD * 2), Dg + (size_t)(k0 + 16) * HID);
    };

    float acc[2][8][4];
#pragma unroll
    for (int i = 0; i < 2; i++)
#pragma unroll
        for (int j = 0; j < 8; j++)
#pragma unroll
            for (int k = 0; k < 4; k++) acc[i][j][k] = 0.f;

    int wm = (wid & 3) * 32;
    int wn = (wid >> 2) * 64;

    unsigned aLd = sb + ((wm + (lane & 7) + ((lane >> 3) & 1) * 8) * STRA
                         + ((lane >> 4) & 1) * 8) * 2;
    unsigned bLd = sb + (AH + ((lane & 7) + ((lane >> 3) & 1) * 8) * BSTRD
                         + wn + ((lane >> 4) & 1) * 8) * 2;

    stage(0, 0);       CP_COMMIT();
    stage(1, BK);      CP_COMMIT();
    stage(2, 2 * BK);  CP_COMMIT();

    const int nch = IEXP / BK;           // 32
    int s = 0;
    for (int i = 0; i < nch; i++) {
        CP_WAIT2();
        __syncthreads();
        if (i + 3 < nch) {
            int s3 = s + 3; if (s3 >= NST) s3 -= NST;
            stage(s3, (i + 3) * BK);
        }
        CP_COMMIT();

        unsigned stOff = (unsigned)s * (STGH_D * 2);
#pragma unroll
        for (int kk = 0; kk < 2; kk++) {
            unsigned af[2][4];
#pragma unroll
            for (int mi = 0; mi < 2; mi++)
                LDSM4(af[mi][0], af[mi][1], af[mi][2], af[mi][3],
                      aLd + stOff + mi * (16 * STRA * 2) + kk * 32);
#pragma unroll
            for (int p = 0; p < 4; p++) {
                unsigned b0, b1, b2, b3;
                LDSM4T(b0, b1, b2, b3,
                       bLd + stOff + kk * (16 * BSTRD * 2) + p * 32);
                unsigned bf0[2] = { b0, b1 }, bf1[2] = { b2, b3 };
#pragma unroll
                for (int mi = 0; mi < 2; mi++) {
                    mma_h(acc[mi][2 * p],     af[mi], bf0);
                    mma_h(acc[mi][2 * p + 1], af[mi], bf1);
                }
            }
        }
        s = (s + 1 == NST) ? 0 : s + 1;
    }

    // scatter rows by token id
#pragma unroll
    for (int mi = 0; mi < 2; mi++) {
        int rb = wm + mi * 16 + (lane >> 2);
#pragma unroll
        for (int ni = 0; ni < 8; ni++) {
            int cc = n0 + wn + ni * 8 + (lane & 3) * 2;
#pragma unroll
            for (int h = 0; h < 2; h++) {
                int r = rb + h * 8;
                if (r < valid) {
                    float* row = out + (size_t)toks[r] * HID;
                    row[cc]     = acc[mi][ni][h * 2];
                    row[cc + 1] = acc[mi][ni][h * 2 + 1];
                }
            }
        }
    }
}

// ---------------- launch ----------------
extern "C" void kernel_launch(void* const* d_in, const int* in_sizes, int n_in,
                              void* d_out, int out_size)
{
    const float* hs   = (const float*)d_in[0];
    const int*   ids  = (const int*)d_in[1];
    const float* gate = (const float*)d_in[2];
    const float* up   = (const float*)d_in[3];
    const float* down = (const float*)d_in[4];
    float*       out  = (float*)d_out;

    cudaFuncSetAttribute(k_mlp,  cudaFuncAttributeMaxDynamicSharedMemorySize, SMB_F);
    cudaFuncSetAttribute(k_down, cudaFuncAttributeMaxDynamicSharedMemorySize, SMB_D);

    k_route<<<1, 256>>>(ids);
    k_prep<<<(T_TOK * HID) / 2048, 256>>>(hs);
    k_wconv<<<dim3((NEXP * HID * IEXP) / 2048, 3), 256>>>(gate, up, down);
    k_mlp <<<dim3(IEXP / 64, 32, NEXP), 256, SMB_F>>>();
    k_down<<<dim3(HID / 128, 32, NEXP), 256, SMB_D>>>(out);
}